// round 2
// baseline (speedup 1.0000x reference)
#include <cuda_runtime.h>
#include <cuda_bf16.h>

// z: [B=16, L=16, H=64, W=64] f32; codes: [L=16, C=64] f32.
// out (f32): soft[B,H,W,L] | hard[B,H,W,L] | idx[B,H,W,L].
#define B_ 16
#define L_ 16
#define H_ 64
#define W_ 64
#define C_ 64
#define N_TOTAL (B_ * L_ * H_ * W_)     // 1,048,576
#define L2E_ 1.44269504088896340736f

// packed f32x2 helpers (sm_103a register-pair ops)
#define PACK2(dst, lo, hi) asm("mov.b64 %0, {%1, %2};" : "=l"(dst) : "f"(lo), "f"(hi))
#define UNPACK2(lo, hi, src) asm("mov.b64 {%0, %1}, %2;" : "=f"(lo), "=f"(hi) : "l"(src))
#define ADD2(d, a, b) asm("add.rn.f32x2 %0, %1, %2;" : "=l"(d) : "l"(a), "l"(b))
#define MUL2(d, a, b) asm("mul.rn.f32x2 %0, %1, %2;" : "=l"(d) : "l"(a), "l"(b))
#define FMA2(d, a, b) asm("fma.rn.f32x2 %0, %1, %2, %0;" : "+l"(d) : "l"(a), "l"(b))
#define EX2(d, s)     asm("ex2.approx.f32 %0, %1;" : "=f"(d) : "f"(s))

typedef unsigned long long u64;

__global__ __launch_bounds__(128)
void soft_to_hard_kernel(const float4* __restrict__ z4,
                         const float* __restrict__ codes,
                         float* __restrict__ out)
{
    // duplicated negated codebook: s_nc[l*64+c] = (-cv, -cv)   (8 KB)
    __shared__ float2 s_nc[L_ * C_];
    for (int k = threadIdx.x; k < L_ * C_; k += 128) {
        float cv = codes[k];
        s_nc[k] = make_float2(-cv, -cv);
    }
    __syncthreads();

    int ti = blockIdx.x * 128 + threadIdx.x;    // over N/4
    float4 zv = z4[ti];                          // 4 consecutive w, same l
    int i  = ti << 2;
    int w0 = i & (W_ - 1);
    int t  = i >> 6;
    int h  = t & (H_ - 1);
    t >>= 6;
    int l  = t & (L_ - 1);
    int b  = t >> 4;

    const float2* __restrict__ cw = &s_nc[l << 6];

    u64 zp01, zp23, kpair;
    PACK2(zp01, zv.x, zv.y);
    PACK2(zp23, zv.z, zv.w);
    PACK2(kpair, L2E_, L2E_);

    u64 sum01 = 0ull, sum23 = 0ull;   // (0.0f, 0.0f)
    u64 acc01 = 0ull, acc23 = 0ull;   // accumulates sum(e * (-cv))
    float dmin0 = 3.402823466e38f, dmin1 = dmin0, dmin2 = dmin0, dmin3 = dmin0;
    int im0 = 0, im1 = 0, im2 = 0, im3 = 0;

    #pragma unroll 16
    for (int c = 0; c < C_; ++c) {
        u64 ncv = *(const u64*)&cw[c];           // LDS.64: (-cv, -cv)

        u64 a01, a23, t01, t23;
        ADD2(a01, zp01, ncv);                    // a = z - cv (exact, packed)
        ADD2(a23, zp23, ncv);
        MUL2(t01, a01, kpair);                   // t = a * log2(e)
        MUL2(t23, a23, kpair);

        float a0, a1, a2, a3, t0, t1, t2, t3;
        UNPACK2(a0, a1, a01);
        UNPACK2(a2, a3, a23);
        UNPACK2(t0, t1, t01);
        UNPACK2(t2, t3, t23);

        float e0, e1, e2, e3;
        EX2(e0, -fabsf(t0));                     // e = 2^(-|a|*log2e) = exp(-|z-cv|)
        EX2(e1, -fabsf(t1));
        EX2(e2, -fabsf(t2));
        EX2(e3, -fabsf(t3));

        u64 e01, e23;
        PACK2(e01, e0, e1);
        PACK2(e23, e2, e3);
        ADD2(sum01, sum01, e01);
        ADD2(sum23, sum23, e23);
        FMA2(acc01, e01, ncv);                   // acc += e * (-cv)
        FMA2(acc23, e23, ncv);

        // exact argmin on d = |z - cv| (same arithmetic as reference; strict '<'
        // preserves first-occurrence tie-break). |a| folds into FSETP/FMNMX mods.
        float d0 = fabsf(a0), d1 = fabsf(a1), d2 = fabsf(a2), d3 = fabsf(a3);
        if (d0 < dmin0) { dmin0 = d0; im0 = c; }
        if (d1 < dmin1) { dmin1 = d1; im1 = c; }
        if (d2 < dmin2) { dmin2 = d2; im2 = c; }
        if (d3 < dmin3) { dmin3 = d3; im3 = c; }
    }

    float s0, s1, s2, s3, q0, q1, q2, q3;
    UNPACK2(s0, s1, sum01);
    UNPACK2(s2, s3, sum23);
    UNPACK2(q0, q1, acc01);
    UNPACK2(q2, q3, acc23);

    int oi = ((b * H_ + h) * W_ + w0) * L_ + l;   // [B,H,W,L]; elems at +0,+16,+32,+48

    // soft = sum(e*cv)/sum(e) = -q/s
    out[oi +  0] = __fdividef(-q0, s0);
    out[oi + 16] = __fdividef(-q1, s1);
    out[oi + 32] = __fdividef(-q2, s2);
    out[oi + 48] = __fdividef(-q3, s3);

    float* outh = out + N_TOTAL;
    outh[oi +  0] = -cw[im0].x;                  // hard = cv at argmin
    outh[oi + 16] = -cw[im1].x;
    outh[oi + 32] = -cw[im2].x;
    outh[oi + 48] = -cw[im3].x;

    float* outi = out + 2 * N_TOTAL;
    outi[oi +  0] = (float)im0;
    outi[oi + 16] = (float)im1;
    outi[oi + 32] = (float)im2;
    outi[oi + 48] = (float)im3;
}

extern "C" void kernel_launch(void* const* d_in, const int* in_sizes, int n_in,
                              void* d_out, int out_size)
{
    const float4* z4   = (const float4*)d_in[0];
    const float* codes = (const float*)d_in[1];
    float* out         = (float*)d_out;

    soft_to_hard_kernel<<<N_TOTAL / (128 * 4), 128>>>(z4, codes, out);
}

// round 4
// speedup vs baseline: 1.8752x; 1.8752x over previous
#include <cuda_runtime.h>
#include <cuda_bf16.h>

// z: [B=16, L=16, H=64, W=64] f32; codes: [L=16, C=64] f32.
// out (f32): soft[B,H,W,L] | hard[B,H,W,L] | idx[B,H,W,L]
#define B_ 16
#define L_ 16
#define H_ 64
#define W_ 64
#define C_ 64
#define N_TOTAL (B_ * L_ * H_ * W_)     // 1,048,576
#define L2E_ 1.442695040888963f

#define EX2(d, s) asm("ex2.approx.f32 %0, %1;" : "=f"(d) : "f"(s))

// Per-l tables built by setup kernel:
//   g_sorted[l][j]      : codes of row l, ascending (stable by original index)
//   g_so[l][j]          : (sorted value, original index as float)
//   g_tab[l][k], k=0..64: (P[k], S[k], P2[k], S2[k])
//     P[k]  = sum_{j<k}  exp(c_j)        S[k]  = sum_{j>=k} exp(-c_j)
//     P2[k] = sum_{j<k}  c_j*exp(c_j)    S2[k] = sum_{j>=k} c_j*exp(-c_j)
// For element z with k = #codes <= z:
//   sum(e)   = exp(-z)*P[k]  + exp(z)*S[k]
//   sum(e*c) = exp(-z)*P2[k] + exp(z)*S2[k]     (exact identity at any split)
__device__ float  g_sorted[L_ * C_];
__device__ float2 g_so[L_ * C_];
__device__ float4 g_tab[L_ * (C_ + 1)];

__global__ void stqh_setup(const float* __restrict__ codes)
{
    int l = blockIdx.x, j = threadIdx.x;     // 16 blocks x 64 threads
    __shared__ float   sc[C_], ss[C_];
    __shared__ int     so[C_];
    __shared__ double2 sp[C_], sf[C_];

    float c = codes[(l << 6) + j];
    sc[j] = c;
    __syncthreads();

    // rank sort (stable): rank = #(ci < c) + #(ci == c, i < j)
    int r = 0;
    #pragma unroll
    for (int i = 0; i < C_; ++i) {
        float ci = sc[i];
        r += (ci < c || (ci == c && i < j)) ? 1 : 0;
    }
    ss[r] = c;
    so[r] = j;
    __syncthreads();

    float v   = ss[j];
    float epf = expf(v);
    float emf = expf(-v);
    sp[j] = make_double2((double)epf, (double)v * (double)epf);
    sf[j] = make_double2((double)emf, (double)v * (double)emf);
    __syncthreads();

    // Hillis-Steele inclusive scans (prefix on sp, suffix on sf), f64
    for (int off = 1; off < C_; off <<= 1) {
        double2 ap = make_double2(0.0, 0.0), af = make_double2(0.0, 0.0);
        if (j >= off)     ap = sp[j - off];
        if (j + off < C_) af = sf[j + off];
        __syncthreads();
        sp[j].x += ap.x; sp[j].y += ap.y;
        sf[j].x += af.x; sf[j].y += af.y;
        __syncthreads();
    }

    double2 pe = (j > 0) ? sp[j - 1] : make_double2(0.0, 0.0);  // exclusive prefix
    double2 se = sf[j];                                          // inclusive suffix
    g_tab[l * (C_ + 1) + j] = make_float4((float)pe.x, (float)se.x,
                                          (float)pe.y, (float)se.y);
    if (j == C_ - 1) {
        double2 tot = sp[C_ - 1];
        g_tab[l * (C_ + 1) + C_] = make_float4((float)tot.x, 0.f, (float)tot.y, 0.f);
    }
    g_sorted[(l << 6) + j] = v;
    g_so[(l << 6) + j]     = make_float2(v, (float)so[j]);
}

// Each block handles 2 output slabs (b,h) of 1024 elements each.
// Thread t covers out positions p = 4t..4t+3 of a slab: same w, l = l0..l0+3.
__global__ __launch_bounds__(256)
void stqh_main(const float* __restrict__ z, float* __restrict__ out)
{
    __shared__ float  s_sorted[L_ * C_];          // 4 KB
    __shared__ float2 s_so[L_ * C_];              // 8 KB
    __shared__ float4 s_tab[L_ * (C_ + 1)];       // 16.25 KB

    int tid = threadIdx.x;
    for (int k = tid; k < L_ * C_; k += 256) {
        s_sorted[k] = g_sorted[k];
        s_so[k]     = g_so[k];
    }
    for (int k = tid; k < L_ * (C_ + 1); k += 256)
        s_tab[k] = g_tab[k];
    __syncthreads();

    int sb = blockIdx.x * 2;          // first slab id = b*64 + h
    int b  = sb >> 6;
    int h0 = sb & 63;

    int p0 = tid << 2;
    int l0 = p0 & 15;
    int w  = p0 >> 4;

    // prefetch z for both slabs (sector-coalesced within warp)
    float zv[2][4];
    #pragma unroll
    for (int s = 0; s < 2; ++s)
        #pragma unroll
        for (int j = 0; j < 4; ++j)
            zv[s][j] = z[((b * L_ + l0 + j) * H_ + (h0 + s)) * W_ + w];

    #pragma unroll
    for (int s = 0; s < 2; ++s) {
        float rs[4], rh[4], ri[4];
        #pragma unroll
        for (int j = 0; j < 4; ++j) {
            int   l  = l0 + j;
            float zz = zv[s][j];
            const float*  srt = s_sorted + (l << 6);
            const float2* so  = s_so     + (l << 6);

            // branchless count of codes <= zz; offsets 32,16,8,4,2,1,1 (sum 64)
            int k = (srt[31] <= zz) ? 32 : 0;
            if (srt[k + 15] <= zz) k += 16;
            if (srt[k +  7] <= zz) k += 8;
            if (srt[k +  3] <= zz) k += 4;
            if (srt[k +  1] <= zz) k += 2;
            if (srt[k]      <= zz) k += 1;
            if (srt[k]      <= zz) k += 1;

            float4 tb = s_tab[l * (C_ + 1) + k];
            float t  = zz * L2E_;
            float ep, em;
            EX2(ep, t);         // exp(zz)
            EX2(em, -t);        // exp(-zz)
            float sum = fmaf(ep, tb.y, em * tb.x);
            float acc = fmaf(ep, tb.w, em * tb.z);
            rs[j] = __fdividef(acc, sum);

            // nearest code: bracketing sorted neighbors, exact ref semantics
            float dL = __int_as_float(0x7f800000), dR = dL;
            float2 cL = make_float2(0.f, 0.f), cR = cL;
            if (k > 0)  { cL = so[k - 1]; dL = fabsf(zz - cL.x); }
            if (k < C_) { cR = so[k];     dR = fabsf(zz - cR.x); }
            bool left = (dL < dR) || (dL == dR && cL.y < cR.y);
            rh[j] = left ? cL.x : cR.x;
            ri[j] = left ? cL.y : cR.y;
        }
        int base = (sb + s) * 1024 + p0;   // out slab offset, 16B aligned
        *(float4*)(out + base)               = make_float4(rs[0], rs[1], rs[2], rs[3]);
        *(float4*)(out + N_TOTAL + base)     = make_float4(rh[0], rh[1], rh[2], rh[3]);
        *(float4*)(out + 2 * N_TOTAL + base) = make_float4(ri[0], ri[1], ri[2], ri[3]);
    }
}

extern "C" void kernel_launch(void* const* d_in, const int* in_sizes, int n_in,
                              void* d_out, int out_size)
{
    const float* zp    = (const float*)d_in[0];
    const float* codes = (const float*)d_in[1];
    float* out         = (float*)d_out;

    stqh_setup<<<L_, C_>>>(codes);
    stqh_main<<<(B_ * H_) / 2, 256>>>(zp, out);
}